// round 5
// baseline (speedup 1.0000x reference)
#include <cuda_runtime.h>
#include <cstdint>

#define N_NODES 90000
#define N_EDGES 540000
#define IN_F    30
#define N_GRAPH 10000

// ======================= global scratch =======================
__device__ float g_agg0[N_NODES * 32];     // x + sum(x[src]), padded to 32
__device__ float g_agg1s[N_NODES * 128];
__device__ float g_agg1t[N_NODES * 128];
__device__ float g_z1s[N_NODES * 128];
__device__ float g_z1t[N_NODES * 128];
__device__ float g_z2s[N_NODES * 64];
__device__ float g_z2t[N_NODES * 64];
__device__ int g_deg[N_NODES];
__device__ int g_cursor[N_NODES];
__device__ int g_rowptr[N_NODES + 1];
__device__ int g_csrsrc[N_EDGES];

// ======================= f32x2 helpers (sm_100+ packed fp32 pipe) =======================
__device__ __forceinline__ unsigned long long dup2(float v) {
    unsigned long long r;
    asm("mov.b64 %0, {%1, %1};" : "=l"(r) : "f"(v));
    return r;
}
__device__ __forceinline__ void fma2(unsigned long long& d, unsigned long long a, unsigned long long b) {
    asm("fma.rn.f32x2 %0, %1, %2, %0;" : "+l"(d) : "l"(a), "l"(b));
}
__device__ __forceinline__ float2 unpk(unsigned long long v) {
    float2 f;
    asm("mov.b64 {%0, %1}, %2;" : "=f"(f.x), "=f"(f.y) : "l"(v));
    return f;
}

// ======================= CSR build =======================
__global__ void zero_kernel() {
    int i = blockIdx.x * blockDim.x + threadIdx.x;
    if (i < N_NODES) { g_deg[i] = 0; g_cursor[i] = 0; }
}
__global__ void hist_kernel(const int* __restrict__ ei) {
    int e = blockIdx.x * blockDim.x + threadIdx.x;
    if (e < N_EDGES) atomicAdd(&g_deg[ei[N_EDGES + e]], 1);
}
__global__ void scan_kernel() {
    const int CHUNK = (N_NODES + 1023) / 1024;
    __shared__ int part[1024];
    int t = threadIdx.x;
    int start = t * CHUNK;
    int s = 0;
    for (int i = 0; i < CHUNK; i++) {
        int idx = start + i;
        if (idx < N_NODES) s += g_deg[idx];
    }
    part[t] = s;
    __syncthreads();
    for (int off = 1; off < 1024; off <<= 1) {
        int v = (t >= off) ? part[t - off] : 0;
        __syncthreads();
        part[t] += v;
        __syncthreads();
    }
    int run = (t > 0) ? part[t - 1] : 0;
    for (int i = 0; i < CHUNK; i++) {
        int idx = start + i;
        if (idx < N_NODES) { g_rowptr[idx] = run; run += g_deg[idx]; }
    }
    if (t == 1023) g_rowptr[N_NODES] = part[1023];
}
__global__ void fill_kernel(const int* __restrict__ ei) {
    int e = blockIdx.x * blockDim.x + threadIdx.x;
    if (e < N_EDGES) {
        int src = ei[e];
        int dst = ei[N_EDGES + e];
        int pos = g_rowptr[dst] + atomicAdd(&g_cursor[dst], 1);
        g_csrsrc[pos] = src;
    }
}

// ======================= layer-1 aggregation -> fp32 [node][32] =======================
__global__ void agg0_kernel(const float* __restrict__ x) {
    int w = (blockIdx.x * blockDim.x + threadIdx.x) >> 5;
    int lane = threadIdx.x & 31;
    if (w >= N_NODES) return;
    float acc = (lane < IN_F) ? x[w * IN_F + lane] : 0.f;
    int s0 = g_rowptr[w], s1 = g_rowptr[w + 1];
    for (int e = s0; e < s1; e++) {
        int s = g_csrsrc[e];
        if (lane < IN_F) acc += x[s * IN_F + lane];
    }
    g_agg0[w * 32 + lane] = acc;
}

// ======================= layer-2 aggregation (both branches, blockIdx.y) =======================
__global__ void agg1_kernel() {
    int br = blockIdx.y;
    const float4* z = (const float4*)(br ? g_z1t : g_z1s);
    float4* a = (float4*)(br ? g_agg1t : g_agg1s);
    int w = (blockIdx.x * blockDim.x + threadIdx.x) >> 5;
    int lane = threadIdx.x & 31;
    if (w >= N_NODES) return;
    float4 acc = z[(size_t)w * 32 + lane];
    int s0 = g_rowptr[w], s1 = g_rowptr[w + 1];
    for (int e = s0; e < s1; e++) {
        int s = g_csrsrc[e];
        float4 v = z[(size_t)s * 32 + lane];
        acc.x += v.x; acc.y += v.y; acc.z += v.z; acc.w += v.w;
    }
    a[(size_t)w * 32 + lane] = acc;
}

// ======================= fused 2-layer MLP via fma.rn.f32x2 =======================
// pass1: H = relu(A[128 x K1] @ W1 + b1)  (128 wide)  -> smem
// pass2: Z = H[128 x 128] @ W2 + b2  (NOUT2 = 16*NPAIR2 wide) -> global
// Thread (tx = tid&7, ty = tid>>3): rows ty*4+{0..3}; col pairs j = 32g + tx*4 + 2e.
template<int K1, int NPAIR2>
__global__ __launch_bounds__(256) void mlp_kernel(
    const float* __restrict__ W1a, const float* __restrict__ W1b,
    const float* __restrict__ B1a, const float* __restrict__ B1b,
    const float* __restrict__ W2a, const float* __restrict__ W2b,
    const float* __restrict__ B2a, const float* __restrict__ B2b,
    int Kreal1)
{
    constexpr int P1 = K1 + 2;           // A pitch (even -> 8B-aligned float2 staging)
    constexpr int P2 = 130;              // H pitch
    constexpr int AOFF = 128 * 130;      // W region float offset (66560 B)
    constexpr int NOUT2 = 16 * NPAIR2;   // 128 or 64
    extern __shared__ float sm[];
    float* a_s = sm;
    float* w_s = sm + AOFF;

    int tid = threadIdx.x;
    int tx = tid & 7;
    int ty = tid >> 3;
    int by = blockIdx.y;
    int row0 = blockIdx.x * 128;

    const float* A;
    float* O;
    if (K1 == 32) { A = g_agg0;                     O = by ? g_z1t : g_z1s; }
    else          { A = by ? g_agg1t : g_agg1s;     O = by ? g_z2t : g_z2s; }
    const float* W1 = by ? W1b : W1a;
    const float* B1 = by ? B1b : B1a;
    const float* W2 = by ? W2b : W2a;
    const float* B2 = by ? B2b : B2a;

    // ---- stage A [128 x K1] row-major pitch P1 ----
    {
        constexpr int C4 = K1 / 4;
        for (int i = tid; i < 128 * C4; i += 256) {
            int r = i / C4, k0 = (i % C4) * 4;
            float4 v = make_float4(0.f, 0.f, 0.f, 0.f);
            int gr = row0 + r;
            if (gr < N_NODES) v = *(const float4*)(A + (size_t)gr * K1 + k0);
            float2* d = (float2*)(a_s + r * P1 + k0);
            d[0] = make_float2(v.x, v.y);
            d[1] = make_float2(v.z, v.w);
        }
    }
    // ---- stage W1 [K1 x 128] (zero pad k >= Kreal1) ----
    for (int i = tid; i < K1 * 32; i += 256) {
        int k = i >> 5, j0 = (i & 31) * 4;
        float4 v = make_float4(0.f, 0.f, 0.f, 0.f);
        if (k < Kreal1) v = *(const float4*)(W1 + k * 128 + j0);
        *(float4*)(w_s + k * 128 + j0) = v;
    }
    __syncthreads();

    // ---- pass 1: 128 x 128, 8 col-pairs per thread ----
    unsigned long long acc[4][8];
    #pragma unroll
    for (int i = 0; i < 4; i++)
        #pragma unroll
        for (int p = 0; p < 8; p++) acc[i][p] = 0ull;

    #pragma unroll 2
    for (int k = 0; k < K1; k++) {
        unsigned long long ad[4];
        #pragma unroll
        for (int i = 0; i < 4; i++) ad[i] = dup2(a_s[(ty * 4 + i) * P1 + k]);
        #pragma unroll
        for (int p = 0; p < 8; p++) {
            unsigned long long wv =
                *(const unsigned long long*)(w_s + k * 128 + 32 * (p >> 1) + tx * 4 + 2 * (p & 1));
            #pragma unroll
            for (int i = 0; i < 4; i++) fma2(acc[i][p], ad[i], wv);
        }
    }
    __syncthreads();   // A/W1 reads complete

    // ---- epilogue 1: H = relu(acc + b1) -> a_s pitch P2 ----
    #pragma unroll
    for (int p = 0; p < 8; p++) {
        int j = 32 * (p >> 1) + tx * 4 + 2 * (p & 1);
        float2 bv = *(const float2*)(B1 + j);
        #pragma unroll
        for (int i = 0; i < 4; i++) {
            float2 h = unpk(acc[i][p]);
            h.x = fmaxf(h.x + bv.x, 0.f);
            h.y = fmaxf(h.y + bv.y, 0.f);
            *(float2*)(a_s + (ty * 4 + i) * P2 + j) = h;
        }
    }
    // ---- stage W2 [128 x NOUT2] ----
    {
        constexpr int C4 = NOUT2 / 4;
        for (int i = tid; i < 128 * C4; i += 256) {
            int k = i / C4, j0 = (i % C4) * 4;
            *(float4*)(w_s + k * NOUT2 + j0) = *(const float4*)(W2 + k * NOUT2 + j0);
        }
    }
    __syncthreads();

    // ---- pass 2: 128 x NOUT2, K = 128 ----
    unsigned long long acc2[4][NPAIR2];
    #pragma unroll
    for (int i = 0; i < 4; i++)
        #pragma unroll
        for (int p = 0; p < NPAIR2; p++) acc2[i][p] = 0ull;

    #pragma unroll 2
    for (int k = 0; k < 128; k++) {
        unsigned long long ad[4];
        #pragma unroll
        for (int i = 0; i < 4; i++) ad[i] = dup2(a_s[(ty * 4 + i) * P2 + k]);
        #pragma unroll
        for (int p = 0; p < NPAIR2; p++) {
            unsigned long long wv =
                *(const unsigned long long*)(w_s + k * NOUT2 + 32 * (p >> 1) + tx * 4 + 2 * (p & 1));
            #pragma unroll
            for (int i = 0; i < 4; i++) fma2(acc2[i][p], ad[i], wv);
        }
    }

    // ---- epilogue 2: out = acc2 + b2 -> global fp32 ----
    #pragma unroll
    for (int g = 0; g < NPAIR2 / 2; g++) {
        int j = 32 * g + tx * 4;
        float4 bv = *(const float4*)(B2 + j);
        #pragma unroll
        for (int i = 0; i < 4; i++) {
            int gr = row0 + ty * 4 + i;
            if (gr < N_NODES) {
                float2 u0 = unpk(acc2[i][2 * g]);
                float2 u1 = unpk(acc2[i][2 * g + 1]);
                float4 o = make_float4(u0.x + bv.x, u0.y + bv.y, u1.x + bv.z, u1.y + bv.w);
                *(float4*)(O + (size_t)gr * NOUT2 + j) = o;
            }
        }
    }
}

// ======================= per-graph 9x9 gram =======================
__global__ void final_kernel(float* __restrict__ out) {
    __shared__ float zs[9 * 64];
    __shared__ float zt[9 * 64];
    int g = blockIdx.x;
    const float4* ps = (const float4*)(g_z2s + (size_t)g * 9 * 64);
    const float4* pt = (const float4*)(g_z2t + (size_t)g * 9 * 64);
    int tid = threadIdx.x;
    for (int i = tid; i < 144; i += 128) {
        ((float4*)zs)[i] = ps[i];
        ((float4*)zt)[i] = pt[i];
    }
    __syncthreads();
    if (tid < 81) {
        int i = tid / 9, j = tid % 9;
        float acc = 0.f;
        #pragma unroll
        for (int k = 0; k < 64; k++) acc += zs[i * 64 + k] * zt[j * 64 + k];
        out[(g * 9 + i) * 9 + j] = acc;
    }
}

// ======================= launch =======================
extern "C" void kernel_launch(void* const* d_in, const int* in_sizes, int n_in,
                              void* d_out, int out_size) {
    const float* x  = (const float*)d_in[0];
    const int*   ei = (const int*)d_in[1];
    const float* w1s = (const float*)d_in[2];
    const float* b1s = (const float*)d_in[3];
    const float* w2s = (const float*)d_in[4];
    const float* b2s = (const float*)d_in[5];
    const float* w3s = (const float*)d_in[6];
    const float* b3s = (const float*)d_in[7];
    const float* w4s = (const float*)d_in[8];
    const float* b4s = (const float*)d_in[9];
    const float* w1t = (const float*)d_in[10];
    const float* b1t = (const float*)d_in[11];
    const float* w2t = (const float*)d_in[12];
    const float* b2t = (const float*)d_in[13];
    const float* w3t = (const float*)d_in[14];
    const float* b3t = (const float*)d_in[15];
    const float* w4t = (const float*)d_in[16];
    const float* b4t = (const float*)d_in[17];
    float* out = (float*)d_out;

    const int SMEM = (128 * 130 + 128 * 128) * 4;   // 132096 bytes
    cudaFuncSetAttribute(mlp_kernel<32, 8>,  cudaFuncAttributeMaxDynamicSharedMemorySize, SMEM);
    cudaFuncSetAttribute(mlp_kernel<128, 4>, cudaFuncAttributeMaxDynamicSharedMemorySize, SMEM);

    const int GEMM_BLOCKS = (N_NODES + 127) / 128;        // 704
    const int WARP_BLOCKS = (N_NODES * 32 + 255) / 256;   // warp-per-node

    // CSR build
    zero_kernel<<<(N_NODES + 255) / 256, 256>>>();
    hist_kernel<<<(N_EDGES + 255) / 256, 256>>>(ei);
    scan_kernel<<<1, 1024>>>();
    fill_kernel<<<(N_EDGES + 255) / 256, 256>>>(ei);

    // layer-1 aggregation (shared by both branches)
    agg0_kernel<<<WARP_BLOCKS, 256>>>(x);

    // layer-1 fused MLP, both branches in one launch
    mlp_kernel<32, 8><<<dim3(GEMM_BLOCKS, 2), 256, SMEM>>>(
        w1s, w1t, b1s, b1t, w2s, w2t, b2s, b2t, IN_F);

    // layer-2 aggregation, both branches
    agg1_kernel<<<dim3(WARP_BLOCKS, 2), 256>>>();

    // layer-2 fused MLP, both branches
    mlp_kernel<128, 4><<<dim3(GEMM_BLOCKS, 2), 256, SMEM>>>(
        w3s, w3t, b3s, b3t, w4s, w4t, b4s, b4t, 128);

    final_kernel<<<N_GRAPH, 128>>>(out);
}

// round 6
// speedup vs baseline: 1.8815x; 1.8815x over previous
#include <cuda_runtime.h>
#include <cuda_bf16.h>
#include <cstdint>

#define N_NODES 90000
#define N_EDGES 540000
#define IN_F    30
#define N_GRAPH 10000

// ======================= global scratch =======================
__device__ __nv_bfloat16 g_agg0_h[N_NODES * 32];
__device__ __nv_bfloat16 g_agg0_l[N_NODES * 32];
__device__ __nv_bfloat16 g_agg1s_h[N_NODES * 128];
__device__ __nv_bfloat16 g_agg1s_l[N_NODES * 128];
__device__ __nv_bfloat16 g_agg1t_h[N_NODES * 128];
__device__ __nv_bfloat16 g_agg1t_l[N_NODES * 128];
__device__ float g_z1s[N_NODES * 128];
__device__ float g_z1t[N_NODES * 128];
__device__ float g_z2s[N_NODES * 64];
__device__ float g_z2t[N_NODES * 64];
__device__ __nv_bfloat16 g_pwh[2][4][128 * 128];   // prepared weights [branch][layer][n][k]
__device__ __nv_bfloat16 g_pwl[2][4][128 * 128];
__device__ int g_deg[N_NODES];
__device__ int g_cursor[N_NODES];
__device__ int g_rowptr[N_NODES + 1];
__device__ int g_csrsrc[N_EDGES];
__device__ int g_bsum[128];
__device__ int g_boff[128];

__device__ __forceinline__ void bf16_split(float v, __nv_bfloat16& h, __nv_bfloat16& l) {
    h = __float2bfloat16(v);
    l = __float2bfloat16(v - __bfloat162float(h));
}
__device__ __forceinline__ void split_pack(float v0, float v1, uint32_t& hi, uint32_t& lo) {
    __nv_bfloat16 h0, l0, h1, l1;
    bf16_split(v0, h0, l0);
    bf16_split(v1, h1, l1);
    __nv_bfloat162 ph; ph.x = h0; ph.y = h1;
    __nv_bfloat162 pl; pl.x = l0; pl.y = l1;
    hi = *(uint32_t*)&ph; lo = *(uint32_t*)&pl;
}

// bf16 tensor-core MMA, fp32 accumulate (family-portable, sm_80+)
__device__ __forceinline__ void mma16816(float* d, const uint32_t* a, const uint32_t* b) {
    asm volatile(
        "mma.sync.aligned.m16n8k16.row.col.f32.bf16.bf16.f32 "
        "{%0,%1,%2,%3}, {%4,%5,%6,%7}, {%8,%9}, {%0,%1,%2,%3};\n"
        : "+f"(d[0]), "+f"(d[1]), "+f"(d[2]), "+f"(d[3])
        : "r"(a[0]), "r"(a[1]), "r"(a[2]), "r"(a[3]), "r"(b[0]), "r"(b[1]));
}
// ldmatrix x4 (sm_75+). Distribution: reg i <- 8x8 matrix addressed by lane group i,
// lane l within matrix gets halfs (row l/4, col 2*(l%4)).
#define LDSM4(r0, r1, r2, r3, addr) \
    asm volatile("ldmatrix.sync.aligned.m8n8.x4.shared.b16 {%0,%1,%2,%3}, [%4];" \
        : "=r"(r0), "=r"(r1), "=r"(r2), "=r"(r3) : "r"(addr))

__device__ __forceinline__ uint32_t smem_u32(const void* p) {
    uint32_t a;
    asm("{ .reg .u64 t; cvta.to.shared.u64 t, %1; cvt.u32.u64 %0, t; }" : "=r"(a) : "l"(p));
    return a;
}

// ======================= CSR build =======================
__global__ void zero_kernel() {
    int i = blockIdx.x * blockDim.x + threadIdx.x;
    if (i < N_NODES) { g_deg[i] = 0; g_cursor[i] = 0; }
}
__global__ void hist_kernel(const int* __restrict__ ei) {
    int e = blockIdx.x * blockDim.x + threadIdx.x;
    if (e < N_EDGES) atomicAdd(&g_deg[ei[N_EDGES + e]], 1);
}
// multi-block scan: 88 blocks x 1024, coalesced
__global__ void scan1_kernel() {
    __shared__ int sm[1024];
    int t = threadIdx.x;
    int idx = blockIdx.x * 1024 + t;
    int d = (idx < N_NODES) ? g_deg[idx] : 0;
    sm[t] = d;
    __syncthreads();
    #pragma unroll
    for (int off = 1; off < 1024; off <<= 1) {
        int v = (t >= off) ? sm[t - off] : 0;
        __syncthreads();
        sm[t] += v;
        __syncthreads();
    }
    if (idx < N_NODES) g_rowptr[idx] = sm[t] - d;   // block-local exclusive
    if (t == 1023) g_bsum[blockIdx.x] = sm[1023];
}
__global__ void scan2_kernel(int nblocks) {
    __shared__ int sm[128];
    int t = threadIdx.x;
    int v = (t < nblocks) ? g_bsum[t] : 0;
    sm[t] = v;
    __syncthreads();
    #pragma unroll
    for (int off = 1; off < 128; off <<= 1) {
        int u = (t >= off) ? sm[t - off] : 0;
        __syncthreads();
        sm[t] += u;
        __syncthreads();
    }
    if (t < nblocks) g_boff[t] = sm[t] - v;
    if (t == nblocks - 1) g_rowptr[N_NODES] = sm[t];
}
__global__ void scan3_kernel() {
    int idx = blockIdx.x * 1024 + threadIdx.x;
    if (idx < N_NODES) g_rowptr[idx] += g_boff[blockIdx.x];
}
__global__ void fill_kernel(const int* __restrict__ ei) {
    int e = blockIdx.x * blockDim.x + threadIdx.x;
    if (e < N_EDGES) {
        int src = ei[e];
        int dst = ei[N_EDGES + e];
        int pos = g_rowptr[dst] + atomicAdd(&g_cursor[dst], 1);
        g_csrsrc[pos] = src;
    }
}

// ======================= weight prep: W[K x N] fp32 -> [n][k] bf16 hi/lo (transposed, K padded)
__global__ void prep_kernel(const float* __restrict__ W, int Kreal, int Nout, int br, int li,
                            int Ksm) {
    int n = blockIdx.x;
    int k = threadIdx.x;
    if (n >= Nout || k >= Ksm) return;
    float v = (k < Kreal) ? W[k * Nout + n] : 0.f;
    __nv_bfloat16 h, l;
    bf16_split(v, h, l);
    g_pwh[br][li][n * Ksm + k] = h;
    g_pwl[br][li][n * Ksm + k] = l;
}

// ======================= layer-1 aggregation -> bf16 hi/lo, K padded to 32
__global__ void agg0_kernel(const float* __restrict__ x) {
    int w = (blockIdx.x * blockDim.x + threadIdx.x) >> 5;
    int lane = threadIdx.x & 31;
    if (w >= N_NODES) return;
    float acc = (lane < IN_F) ? x[w * IN_F + lane] : 0.f;
    int s0 = g_rowptr[w], s1 = g_rowptr[w + 1];
    for (int e = s0; e < s1; e++) {
        int s = g_csrsrc[e];
        if (lane < IN_F) acc += x[s * IN_F + lane];
    }
    __nv_bfloat16 h, l;
    bf16_split(acc, h, l);
    g_agg0_h[w * 32 + lane] = h;
    g_agg0_l[w * 32 + lane] = l;
}

// ======================= layer-2 aggregation, BOTH branches in one pass =======================
__global__ void agg1_kernel() {
    const float4* zs = (const float4*)g_z1s;
    const float4* zt = (const float4*)g_z1t;
    int w = (blockIdx.x * blockDim.x + threadIdx.x) >> 5;
    int lane = threadIdx.x & 31;
    if (w >= N_NODES) return;
    float4 as = zs[(size_t)w * 32 + lane];
    float4 at = zt[(size_t)w * 32 + lane];
    int s0 = g_rowptr[w], s1 = g_rowptr[w + 1];
    for (int e = s0; e < s1; e++) {
        int s = g_csrsrc[e];
        float4 vs = zs[(size_t)s * 32 + lane];
        float4 vt = zt[(size_t)s * 32 + lane];
        as.x += vs.x; as.y += vs.y; as.z += vs.z; as.w += vs.w;
        at.x += vt.x; at.y += vt.y; at.z += vt.z; at.w += vt.w;
    }
    uint32_t h01, l01, h23, l23;
    split_pack(as.x, as.y, h01, l01);
    split_pack(as.z, as.w, h23, l23);
    uint32_t* oh = (uint32_t*)(g_agg1s_h + (size_t)w * 128 + lane * 4);
    uint32_t* ol = (uint32_t*)(g_agg1s_l + (size_t)w * 128 + lane * 4);
    oh[0] = h01; oh[1] = h23;
    ol[0] = l01; ol[1] = l23;
    split_pack(at.x, at.y, h01, l01);
    split_pack(at.z, at.w, h23, l23);
    oh = (uint32_t*)(g_agg1t_h + (size_t)w * 128 + lane * 4);
    ol = (uint32_t*)(g_agg1t_l + (size_t)w * 128 + lane * 4);
    oh[0] = h01; oh[1] = h23;
    ol[0] = l01; ol[1] = l23;
}

// ======================= fused 2-layer MLP: ldmatrix + mma.sync =======================
// pass1: H = relu(A[128 x K1] @ W1^T + b1) -> smem (bf16 hi/lo)
// pass2: Z = H[128 x 128] @ W2^T + b2 (NOUT2 = NT2*16) -> global fp32
// split precision: D = Ah*Bh + Ah*Bl + Al*Bh
// Both branches per launch via blockIdx.y.
template<int K1, int NT2>
__global__ __launch_bounds__(256) void mlp_kernel(
    const float* __restrict__ B1a, const float* __restrict__ B1b,
    const float* __restrict__ B2a, const float* __restrict__ B2b)
{
    constexpr int PK1 = K1 + 8;
    constexpr int PK2 = 136;
    constexpr int TILEH = 128 * PK2;
    constexpr int NOUT2 = NT2 * 16;
    extern __shared__ char smraw[];
    __nv_bfloat16* AH = (__nv_bfloat16*)smraw;
    __nv_bfloat16* AL = AH + TILEH;
    __nv_bfloat16* WH = AL + TILEH;
    __nv_bfloat16* WL = WH + TILEH;

    int tid = threadIdx.x, lane = tid & 31, wid = tid >> 5;
    int warpM = wid & 3, warpN = wid >> 2;
    int by = blockIdx.y;
    int row0 = blockIdx.x * 128;
    int lg = lane >> 2;
    int lt = lane & 3;

    int a_sel = (K1 == 32) ? 0 : 1;
    const __nv_bfloat16* Agh = a_sel ? (by ? g_agg1t_h : g_agg1s_h) : g_agg0_h;
    const __nv_bfloat16* Agl = a_sel ? (by ? g_agg1t_l : g_agg1s_l) : g_agg0_l;
    int l1 = a_sel ? 2 : 0;
    const __nv_bfloat16* W1h = g_pwh[by][l1];
    const __nv_bfloat16* W1l = g_pwl[by][l1];
    const __nv_bfloat16* W2h = g_pwh[by][l1 + 1];
    const __nv_bfloat16* W2l = g_pwl[by][l1 + 1];
    const float* B1 = by ? B1b : B1a;
    const float* B2 = by ? B2b : B2a;

    // ---- load A (K1 wide) and W1 into smem (pitch PK1, pad zeroed) ----
    {
        constexpr int CPR = PK1 / 8;
        for (int i = tid; i < 128 * CPR; i += 256) {
            int r = i / CPR, c = i % CPR, col = c * 8;
            float4 zf = make_float4(0.f, 0.f, 0.f, 0.f);
            float4 vh = zf, vl = zf, wh = zf, wl = zf;
            int gr = row0 + r;
            if (col < K1) {
                if (gr < N_NODES) {
                    vh = *(const float4*)(Agh + (size_t)gr * K1 + col);
                    vl = *(const float4*)(Agl + (size_t)gr * K1 + col);
                }
                wh = *(const float4*)(W1h + r * K1 + col);
                wl = *(const float4*)(W1l + r * K1 + col);
            }
            *(float4*)(AH + r * PK1 + col) = vh;
            *(float4*)(AL + r * PK1 + col) = vl;
            *(float4*)(WH + r * PK1 + col) = wh;
            *(float4*)(WL + r * PK1 + col) = wl;
        }
    }
    __syncthreads();

    // ldmatrix lane->address components.
    // A x4 tile (16x16 at row base R, col base k0): lanes 0-7 rows R+0..7 @k0,
    // 8-15 rows R+8..15 @k0, 16-23 rows R+0..7 @k0+8, 24-31 rows R+8..15 @k0+8.
    int a_row = lane & 15;
    int a_col = (lane >> 4) * 8;
    // B x4 (2 n-tiles of n8k16 at row base N0): lanes 0-7 n N0+0..7 @k0,
    // 8-15 n N0+0..7 @k0+8, 16-23 n N0+8..15 @k0, 24-31 n N0+8..15 @k0+8.
    int b_row = (lane & 7) + ((lane >> 4) & 1) * 8;
    int b_col = ((lane >> 3) & 1) * 8;

    uint32_t uAH = smem_u32(AH), uAL = smem_u32(AL);
    uint32_t uWH = smem_u32(WH), uWL = smem_u32(WL);

    // ---- pass 1: 128 x 128, warp tile 32 x 64 ----
    float acc[2][8][4];
    #pragma unroll
    for (int tm = 0; tm < 2; tm++)
        #pragma unroll
        for (int tn = 0; tn < 8; tn++)
            #pragma unroll
            for (int q = 0; q < 4; q++) acc[tm][tn][q] = 0.f;

    {
        uint32_t aBH[2], aBL[2], bBH[4], bBL[4];
        #pragma unroll
        for (int tm = 0; tm < 2; tm++) {
            int R = warpM * 32 + tm * 16;
            aBH[tm] = uAH + ((R + a_row) * PK1 + a_col) * 2;
            aBL[tm] = uAL + ((R + a_row) * PK1 + a_col) * 2;
        }
        #pragma unroll
        for (int pp = 0; pp < 4; pp++) {
            int N0 = warpN * 64 + pp * 16;
            bBH[pp] = uWH + ((N0 + b_row) * PK1 + b_col) * 2;
            bBL[pp] = uWL + ((N0 + b_row) * PK1 + b_col) * 2;
        }
        #pragma unroll
        for (int ks = 0; ks < K1 / 16; ks++) {
            uint32_t ah[2][4], al[2][4];
            #pragma unroll
            for (int tm = 0; tm < 2; tm++) {
                LDSM4(ah[tm][0], ah[tm][1], ah[tm][2], ah[tm][3], aBH[tm] + ks * 32);
                LDSM4(al[tm][0], al[tm][1], al[tm][2], al[tm][3], aBL[tm] + ks * 32);
            }
            #pragma unroll
            for (int pp = 0; pp < 4; pp++) {
                uint32_t bh[4], bl[4];
                LDSM4(bh[0], bh[1], bh[2], bh[3], bBH[pp] + ks * 32);
                LDSM4(bl[0], bl[1], bl[2], bl[3], bBL[pp] + ks * 32);
                #pragma unroll
                for (int hf = 0; hf < 2; hf++) {
                    int tn = pp * 2 + hf;
                    #pragma unroll
                    for (int tm = 0; tm < 2; tm++) {
                        mma16816(acc[tm][tn], ah[tm], bh + 2 * hf);
                        mma16816(acc[tm][tn], ah[tm], bl + 2 * hf);
                        mma16816(acc[tm][tn], al[tm], bh + 2 * hf);
                    }
                }
            }
        }
    }
    __syncthreads();   // done reading A/W1

    // ---- stage H = relu(acc + b1) -> smem (split hi/lo), pitch PK2 ----
    #pragma unroll
    for (int tm = 0; tm < 2; tm++) {
        int m = warpM * 32 + tm * 16 + lg;
        #pragma unroll
        for (int tn = 0; tn < 8; tn++) {
            int n = warpN * 64 + tn * 8 + lt * 2;
            float2 bv = *(const float2*)(B1 + n);
            float v0 = fmaxf(acc[tm][tn][0] + bv.x, 0.f);
            float v1 = fmaxf(acc[tm][tn][1] + bv.y, 0.f);
            float v2 = fmaxf(acc[tm][tn][2] + bv.x, 0.f);
            float v3 = fmaxf(acc[tm][tn][3] + bv.y, 0.f);
            uint32_t hi, lo;
            split_pack(v0, v1, hi, lo);
            *(uint32_t*)(AH + m * PK2 + n) = hi;
            *(uint32_t*)(AL + m * PK2 + n) = lo;
            split_pack(v2, v3, hi, lo);
            *(uint32_t*)(AH + (m + 8) * PK2 + n) = hi;
            *(uint32_t*)(AL + (m + 8) * PK2 + n) = lo;
        }
    }
    // ---- load W2 (NOUT2 rows x 128) into W region (pitch PK2) ----
    for (int i = tid; i < NOUT2 * 17; i += 256) {
        int r = i / 17, c = i % 17, col = c * 8;
        float4 wh = make_float4(0.f, 0.f, 0.f, 0.f), wl = wh;
        if (col < 128) {
            wh = *(const float4*)(W2h + r * 128 + col);
            wl = *(const float4*)(W2l + r * 128 + col);
        }
        *(float4*)(WH + r * PK2 + col) = wh;
        *(float4*)(WL + r * PK2 + col) = wl;
    }
    __syncthreads();

    // ---- pass 2: 128 x NOUT2, K = 128 ----
    float acc2[2][NT2][4];
    #pragma unroll
    for (int tm = 0; tm < 2; tm++)
        #pragma unroll
        for (int tn = 0; tn < NT2; tn++)
            #pragma unroll
            for (int q = 0; q < 4; q++) acc2[tm][tn][q] = 0.f;

    {
        uint32_t aBH[2], aBL[2], bBH[NT2 / 2], bBL[NT2 / 2];
        #pragma unroll
        for (int tm = 0; tm < 2; tm++) {
            int R = warpM * 32 + tm * 16;
            aBH[tm] = uAH + ((R + a_row) * PK2 + a_col) * 2;
            aBL[tm] = uAL + ((R + a_row) * PK2 + a_col) * 2;
        }
        #pragma unroll
        for (int pp = 0; pp < NT2 / 2; pp++) {
            int N0 = warpN * (NOUT2 / 2) + pp * 16;
            bBH[pp] = uWH + ((N0 + b_row) * PK2 + b_col) * 2;
            bBL[pp] = uWL + ((N0 + b_row) * PK2 + b_col) * 2;
        }
        #pragma unroll
        for (int ks = 0; ks < 8; ks++) {
            uint32_t ah[2][4], al[2][4];
            #pragma unroll
            for (int tm = 0; tm < 2; tm++) {
                LDSM4(ah[tm][0], ah[tm][1], ah[tm][2], ah[tm][3], aBH[tm] + ks * 32);
                LDSM4(al[tm][0], al[tm][1], al[tm][2], al[tm][3], aBL[tm] + ks * 32);
            }
            #pragma unroll
            for (int pp = 0; pp < NT2 / 2; pp++) {
                uint32_t bh[4], bl[4];
                LDSM4(bh[0], bh[1], bh[2], bh[3], bBH[pp] + ks * 32);
                LDSM4(bl[0], bl[1], bl[2], bl[3], bBL[pp] + ks * 32);
                #pragma unroll
                for (int hf = 0; hf < 2; hf++) {
                    int tn = pp * 2 + hf;
                    #pragma unroll
                    for (int tm = 0; tm < 2; tm++) {
                        mma16816(acc2[tm][tn], ah[tm], bh + 2 * hf);
                        mma16816(acc2[tm][tn], ah[tm], bl + 2 * hf);
                        mma16816(acc2[tm][tn], al[tm], bh + 2 * hf);
                    }
                }
            }
        }
    }

    // ---- epilogue: Z + b2 -> global fp32 ----
    float* outF = (K1 == 32) ? (by ? g_z1t : g_z1s) : (by ? g_z2t : g_z2s);
    #pragma unroll
    for (int tm = 0; tm < 2; tm++) {
        int m = warpM * 32 + tm * 16 + lg;
        #pragma unroll
        for (int tn = 0; tn < NT2; tn++) {
            int n = warpN * (NOUT2 / 2) + tn * 8 + lt * 2;
            float2 bv = *(const float2*)(B2 + n);
            int g0 = row0 + m;
            if (g0 < N_NODES) {
                float2 o; o.x = acc2[tm][tn][0] + bv.x; o.y = acc2[tm][tn][1] + bv.y;
                *(float2*)(outF + (size_t)g0 * NOUT2 + n) = o;
            }
            int g1 = row0 + m + 8;
            if (g1 < N_NODES) {
                float2 o; o.x = acc2[tm][tn][2] + bv.x; o.y = acc2[tm][tn][3] + bv.y;
                *(float2*)(outF + (size_t)g1 * NOUT2 + n) = o;
            }
        }
    }
}

// ======================= per-graph 9x9 gram =======================
__global__ void final_kernel(float* __restrict__ out) {
    __shared__ float zs[9 * 64];
    __shared__ float zt[9 * 64];
    int g = blockIdx.x;
    const float4* ps = (const float4*)(g_z2s + (size_t)g * 9 * 64);
    const float4* pt = (const float4*)(g_z2t + (size_t)g * 9 * 64);
    int tid = threadIdx.x;
    for (int i = tid; i < 144; i += 128) {
        ((float4*)zs)[i] = ps[i];
        ((float4*)zt)[i] = pt[i];
    }
    __syncthreads();
    if (tid < 81) {
        int i = tid / 9, j = tid % 9;
        float acc = 0.f;
        #pragma unroll
        for (int k = 0; k < 64; k++) acc += zs[i * 64 + k] * zt[j * 64 + k];
        out[(g * 9 + i) * 9 + j] = acc;
    }
}

// ======================= launch =======================
extern "C" void kernel_launch(void* const* d_in, const int* in_sizes, int n_in,
                              void* d_out, int out_size) {
    const float* x  = (const float*)d_in[0];
    const int*   ei = (const int*)d_in[1];
    const float* W[2][4] = {
        { (const float*)d_in[2],  (const float*)d_in[4],  (const float*)d_in[6],  (const float*)d_in[8]  },
        { (const float*)d_in[10], (const float*)d_in[12], (const float*)d_in[14], (const float*)d_in[16] }
    };
    const float* B[2][4] = {
        { (const float*)d_in[3],  (const float*)d_in[5],  (const float*)d_in[7],  (const float*)d_in[9]  },
        { (const float*)d_in[11], (const float*)d_in[13], (const float*)d_in[15], (const float*)d_in[17] }
    };
    float* out = (float*)d_out;

    const int SMEM = 4 * 128 * 136 * 2;   // 139264 bytes
    cudaFuncSetAttribute(mlp_kernel<32, 8>,  cudaFuncAttributeMaxDynamicSharedMemorySize, SMEM);
    cudaFuncSetAttribute(mlp_kernel<128, 4>, cudaFuncAttributeMaxDynamicSharedMemorySize, SMEM);

    const int GEMM_BLOCKS = (N_NODES + 127) / 128;       // 704
    const int WARP_BLOCKS = (N_NODES * 32 + 255) / 256;
    const int SCAN_BLOCKS = (N_NODES + 1023) / 1024;     // 88

    // CSR build
    zero_kernel<<<(N_NODES + 255) / 256, 256>>>();
    hist_kernel<<<(N_EDGES + 255) / 256, 256>>>(ei);
    scan1_kernel<<<SCAN_BLOCKS, 1024>>>();
    scan2_kernel<<<1, 128>>>(SCAN_BLOCKS);
    scan3_kernel<<<SCAN_BLOCKS, 1024>>>();
    fill_kernel<<<(N_EDGES + 255) / 256, 256>>>(ei);

    // weight prep
    for (int br = 0; br < 2; br++) {
        prep_kernel<<<128, 32>>>(W[br][0], IN_F, 128, br, 0, 32);
        prep_kernel<<<128, 128>>>(W[br][1], 128, 128, br, 1, 128);
        prep_kernel<<<128, 128>>>(W[br][2], 128, 128, br, 2, 128);
        prep_kernel<<<64, 128>>>(W[br][3], 128, 64, br, 3, 128);
    }

    agg0_kernel<<<WARP_BLOCKS, 256>>>(x);

    // layer 1 (fused MLP), both branches in one launch
    mlp_kernel<32, 8><<<dim3(GEMM_BLOCKS, 2), 256, SMEM>>>(B[0][0], B[1][0], B[0][1], B[1][1]);

    // layer 2 aggregation (both branches in one pass)
    agg1_kernel<<<WARP_BLOCKS, 256>>>();

    // layer 2 (fused MLP), both branches in one launch
    mlp_kernel<128, 4><<<dim3(GEMM_BLOCKS, 2), 256, SMEM>>>(B[0][2], B[1][2], B[0][3], B[1][3]);

    final_kernel<<<N_GRAPH, 128>>>(out);
}

// round 9
// speedup vs baseline: 2.0761x; 1.1034x over previous
#include <cuda_runtime.h>
#include <cuda_bf16.h>
#include <cstdint>

#define N_NODES 90000
#define N_EDGES 540000
#define IN_F    30
#define N_GRAPH 10000

// ======================= global scratch =======================
__device__ __nv_bfloat16 g_agg0_h[N_NODES * 32];
__device__ __nv_bfloat16 g_agg0_l[N_NODES * 32];
__device__ __nv_bfloat16 g_agg1s_h[N_NODES * 128];
__device__ __nv_bfloat16 g_agg1s_l[N_NODES * 128];
__device__ __nv_bfloat16 g_agg1t_h[N_NODES * 128];
__device__ __nv_bfloat16 g_agg1t_l[N_NODES * 128];
__device__ float g_z1s[N_NODES * 128];
__device__ float g_z1t[N_NODES * 128];
__device__ float g_z2s[N_NODES * 64];
__device__ float g_z2t[N_NODES * 64];
__device__ __nv_bfloat16 g_pwh[2][4][128 * 128];   // prepared weights [branch][layer][n][k]
__device__ __nv_bfloat16 g_pwl[2][4][128 * 128];
__device__ int g_deg[N_NODES];
__device__ int g_cursor[N_NODES];
__device__ int g_rowptr[N_NODES + 1];
__device__ int g_csrsrc[N_EDGES];
__device__ int g_bsum[128];
__device__ int g_boff[128];

__device__ __forceinline__ void bf16_split(float v, __nv_bfloat16& h, __nv_bfloat16& l) {
    h = __float2bfloat16(v);
    l = __float2bfloat16(v - __bfloat162float(h));
}
__device__ __forceinline__ void split_pack(float v0, float v1, uint32_t& hi, uint32_t& lo) {
    __nv_bfloat16 h0, l0, h1, l1;
    bf16_split(v0, h0, l0);
    bf16_split(v1, h1, l1);
    __nv_bfloat162 ph; ph.x = h0; ph.y = h1;
    __nv_bfloat162 pl; pl.x = l0; pl.y = l1;
    hi = *(uint32_t*)&ph; lo = *(uint32_t*)&pl;
}

// bf16 tensor-core MMA, fp32 accumulate (family-portable, sm_80+)
__device__ __forceinline__ void mma16816(float* d, const uint32_t* a, const uint32_t* b) {
    asm volatile(
        "mma.sync.aligned.m16n8k16.row.col.f32.bf16.bf16.f32 "
        "{%0,%1,%2,%3}, {%4,%5,%6,%7}, {%8,%9}, {%0,%1,%2,%3};\n"
        : "+f"(d[0]), "+f"(d[1]), "+f"(d[2]), "+f"(d[3])
        : "r"(a[0]), "r"(a[1]), "r"(a[2]), "r"(a[3]), "r"(b[0]), "r"(b[1]));
}
#define LDSM4(r0, r1, r2, r3, addr) \
    asm volatile("ldmatrix.sync.aligned.m8n8.x4.shared.b16 {%0,%1,%2,%3}, [%4];" \
        : "=r"(r0), "=r"(r1), "=r"(r2), "=r"(r3) : "r"(addr))

__device__ __forceinline__ uint32_t smem_u32(const void* p) {
    uint32_t a;
    asm("{ .reg .u64 t; cvta.to.shared.u64 t, %1; cvt.u32.u64 %0, t; }" : "=r"(a) : "l"(p));
    return a;
}

// ======================= CSR build =======================
__global__ void zero_kernel() {
    int i = blockIdx.x * blockDim.x + threadIdx.x;
    if (i < N_NODES) { g_deg[i] = 0; g_cursor[i] = 0; }
}
__global__ void hist_kernel(const int* __restrict__ ei) {
    int e = blockIdx.x * blockDim.x + threadIdx.x;
    if (e < N_EDGES) atomicAdd(&g_deg[ei[N_EDGES + e]], 1);
}
__global__ void scan1_kernel() {
    __shared__ int sm[1024];
    int t = threadIdx.x;
    int idx = blockIdx.x * 1024 + t;
    int d = (idx < N_NODES) ? g_deg[idx] : 0;
    sm[t] = d;
    __syncthreads();
    #pragma unroll
    for (int off = 1; off < 1024; off <<= 1) {
        int v = (t >= off) ? sm[t - off] : 0;
        __syncthreads();
        sm[t] += v;
        __syncthreads();
    }
    if (idx < N_NODES) g_rowptr[idx] = sm[t] - d;
    if (t == 1023) g_bsum[blockIdx.x] = sm[1023];
}
__global__ void scan2_kernel(int nblocks) {
    __shared__ int sm[128];
    int t = threadIdx.x;
    int v = (t < nblocks) ? g_bsum[t] : 0;
    sm[t] = v;
    __syncthreads();
    #pragma unroll
    for (int off = 1; off < 128; off <<= 1) {
        int u = (t >= off) ? sm[t - off] : 0;
        __syncthreads();
        sm[t] += u;
        __syncthreads();
    }
    if (t < nblocks) g_boff[t] = sm[t] - v;
    if (t == nblocks - 1) g_rowptr[N_NODES] = sm[t];
}
__global__ void scan3_kernel() {
    int idx = blockIdx.x * 1024 + threadIdx.x;
    if (idx < N_NODES) g_rowptr[idx] += g_boff[blockIdx.x];
}
__global__ void fill_kernel(const int* __restrict__ ei) {
    int e = blockIdx.x * blockDim.x + threadIdx.x;
    if (e < N_EDGES) {
        int src = ei[e];
        int dst = ei[N_EDGES + e];
        int pos = g_rowptr[dst] + atomicAdd(&g_cursor[dst], 1);
        g_csrsrc[pos] = src;
    }
}

// ======================= weight prep, all 8 weights in ONE launch =======================
// blockIdx.y: 0..7 -> (br = y>>2, li = y&3). W[K x N] fp32 -> [n][k] bf16 hi/lo.
// Pointers passed as kernel args (graph-capture safe).
__global__ void prep_all_kernel(
    const float* w0, const float* w1, const float* w2, const float* w3,
    const float* w4, const float* w5, const float* w6, const float* w7)
{
    const int KREAL[4] = { IN_F, 128, 128, 128 };
    const int KSM[4]   = { 32, 128, 128, 128 };
    const int NOUT[4]  = { 128, 128, 128, 64 };
    const float* Ws[8] = { w0, w1, w2, w3, w4, w5, w6, w7 };
    int y = blockIdx.y;
    int br = y >> 2, li = y & 3;
    int n = blockIdx.x;
    int k = threadIdx.x;
    if (n >= NOUT[li] || k >= KSM[li]) return;
    const float* W = Ws[y];
    float v = (k < KREAL[li]) ? W[k * NOUT[li] + n] : 0.f;
    __nv_bfloat16 h, l;
    bf16_split(v, h, l);
    g_pwh[br][li][n * KSM[li] + k] = h;
    g_pwl[br][li][n * KSM[li] + k] = l;
}

// ======================= layer-1 aggregation -> bf16 hi/lo, K padded to 32
__global__ void agg0_kernel(const float* __restrict__ x) {
    int w = (blockIdx.x * blockDim.x + threadIdx.x) >> 5;
    int lane = threadIdx.x & 31;
    if (w >= N_NODES) return;
    float acc = (lane < IN_F) ? x[w * IN_F + lane] : 0.f;
    int s0 = g_rowptr[w], s1 = g_rowptr[w + 1];
    for (int e = s0; e < s1; e++) {
        int s = g_csrsrc[e];
        if (lane < IN_F) acc += x[s * IN_F + lane];
    }
    __nv_bfloat16 h, l;
    bf16_split(acc, h, l);
    g_agg0_h[w * 32 + lane] = h;
    g_agg0_l[w * 32 + lane] = l;
}

// ======================= layer-2 aggregation, BOTH branches in one pass =======================
__global__ void agg1_kernel() {
    const float4* zs = (const float4*)g_z1s;
    const float4* zt = (const float4*)g_z1t;
    int w = (blockIdx.x * blockDim.x + threadIdx.x) >> 5;
    int lane = threadIdx.x & 31;
    if (w >= N_NODES) return;
    float4 as = zs[(size_t)w * 32 + lane];
    float4 at = zt[(size_t)w * 32 + lane];
    int s0 = g_rowptr[w], s1 = g_rowptr[w + 1];
    for (int e = s0; e < s1; e++) {
        int s = g_csrsrc[e];
        float4 vs = zs[(size_t)s * 32 + lane];
        float4 vt = zt[(size_t)s * 32 + lane];
        as.x += vs.x; as.y += vs.y; as.z += vs.z; as.w += vs.w;
        at.x += vt.x; at.y += vt.y; at.z += vt.z; at.w += vt.w;
    }
    uint32_t h01, l01, h23, l23;
    split_pack(as.x, as.y, h01, l01);
    split_pack(as.z, as.w, h23, l23);
    uint32_t* oh = (uint32_t*)(g_agg1s_h + (size_t)w * 128 + lane * 4);
    uint32_t* ol = (uint32_t*)(g_agg1s_l + (size_t)w * 128 + lane * 4);
    oh[0] = h01; oh[1] = h23;
    ol[0] = l01; ol[1] = l23;
    split_pack(at.x, at.y, h01, l01);
    split_pack(at.z, at.w, h23, l23);
    oh = (uint32_t*)(g_agg1t_h + (size_t)w * 128 + lane * 4);
    ol = (uint32_t*)(g_agg1t_l + (size_t)w * 128 + lane * 4);
    oh[0] = h01; oh[1] = h23;
    ol[0] = l01; ol[1] = l23;
}

// ======================= fused 2-layer MLP, M-tile 64 (2 CTA/SM) =======================
// pass1: H = relu(A[64 x K1] @ W1^T + b1) -> smem (bf16 hi/lo), 128 wide
// pass2: Z = H[64 x 128] @ W2^T + b2 (NOUT2 = NT2*32) -> global fp32
// split precision: D = Ah*Bh + Ah*Bl + Al*Bh. Both branches via blockIdx.y.
// 8 warps: warpM = wid&1 (2 x 32 rows), warpN = wid>>1 (4 x N/4 cols)
template<int K1, int NT2>
__global__ __launch_bounds__(256, 2) void mlp_kernel(
    const float* __restrict__ B1a, const float* __restrict__ B1b,
    const float* __restrict__ B2a, const float* __restrict__ B2b)
{
    constexpr int PK1 = K1 + 8;
    constexpr int PK2 = 136;
    constexpr int ATILE = 64 * PK2;       // halfs per A buffer
    constexpr int WTILE = 128 * PK2;      // halfs per W buffer
    constexpr int NOUT2 = NT2 * 32;       // 128 or 64
    extern __shared__ char smraw[];
    __nv_bfloat16* AH = (__nv_bfloat16*)smraw;
    __nv_bfloat16* AL = AH + ATILE;
    __nv_bfloat16* WH = AL + ATILE;
    __nv_bfloat16* WL = WH + WTILE;

    int tid = threadIdx.x, lane = tid & 31, wid = tid >> 5;
    int warpM = wid & 1, warpN = wid >> 1;
    int by = blockIdx.y;
    int row0 = blockIdx.x * 64;
    int lg = lane >> 2;
    int lt = lane & 3;

    int a_sel = (K1 == 32) ? 0 : 1;
    const __nv_bfloat16* Agh = a_sel ? (by ? g_agg1t_h : g_agg1s_h) : g_agg0_h;
    const __nv_bfloat16* Agl = a_sel ? (by ? g_agg1t_l : g_agg1s_l) : g_agg0_l;
    int l1 = a_sel ? 2 : 0;
    const __nv_bfloat16* W1h = g_pwh[by][l1];
    const __nv_bfloat16* W1l = g_pwl[by][l1];
    const __nv_bfloat16* W2h = g_pwh[by][l1 + 1];
    const __nv_bfloat16* W2l = g_pwl[by][l1 + 1];
    const float* B1 = by ? B1b : B1a;
    const float* B2 = by ? B2b : B2a;

    // ---- load A [64 x K1] and W1 [128 x K1] into smem (pitch PK1) ----
    {
        constexpr int CPR = PK1 / 8;
        for (int i = tid; i < 64 * CPR; i += 256) {
            int r = i / CPR, c = i % CPR, col = c * 8;
            float4 zf = make_float4(0.f, 0.f, 0.f, 0.f);
            float4 vh = zf, vl = zf;
            int gr = row0 + r;
            if (col < K1 && gr < N_NODES) {
                vh = *(const float4*)(Agh + (size_t)gr * K1 + col);
                vl = *(const float4*)(Agl + (size_t)gr * K1 + col);
            }
            *(float4*)(AH + r * PK1 + col) = vh;
            *(float4*)(AL + r * PK1 + col) = vl;
        }
        for (int i = tid; i < 128 * CPR; i += 256) {
            int r = i / CPR, c = i % CPR, col = c * 8;
            float4 zf = make_float4(0.f, 0.f, 0.f, 0.f);
            float4 wh = zf, wl = zf;
            if (col < K1) {
                wh = *(const float4*)(W1h + r * K1 + col);
                wl = *(const float4*)(W1l + r * K1 + col);
            }
            *(float4*)(WH + r * PK1 + col) = wh;
            *(float4*)(WL + r * PK1 + col) = wl;
        }
    }
    __syncthreads();

    // ldmatrix lane->addr components (same mapping as verified R3/R5 kernels)
    int a_row = lane & 15;
    int a_col = (lane >> 4) * 8;
    int b_row = (lane & 7) + ((lane >> 4) & 1) * 8;
    int b_col = ((lane >> 3) & 1) * 8;

    uint32_t uAH = smem_u32(AH), uAL = smem_u32(AL);
    uint32_t uWH = smem_u32(WH), uWL = smem_u32(WL);

    // ---- pass 1: 64 x 128, warp tile 32 x 32 ----
    float acc[2][4][4];
    #pragma unroll
    for (int tm = 0; tm < 2; tm++)
        #pragma unroll
        for (int tn = 0; tn < 4; tn++)
            #pragma unroll
            for (int q = 0; q < 4; q++) acc[tm][tn][q] = 0.f;

    {
        uint32_t aBH[2], aBL[2], bBH[2], bBL[2];
        #pragma unroll
        for (int tm = 0; tm < 2; tm++) {
            int R = warpM * 32 + tm * 16;
            aBH[tm] = uAH + ((R + a_row) * PK1 + a_col) * 2;
            aBL[tm] = uAL + ((R + a_row) * PK1 + a_col) * 2;
        }
        #pragma unroll
        for (int pp = 0; pp < 2; pp++) {
            int N0 = warpN * 32 + pp * 16;
            bBH[pp] = uWH + ((N0 + b_row) * PK1 + b_col) * 2;
            bBL[pp] = uWL + ((N0 + b_row) * PK1 + b_col) * 2;
        }
        #pragma unroll
        for (int ks = 0; ks < K1 / 16; ks++) {
            uint32_t ah[2][4], al[2][4];
            #pragma unroll
            for (int tm = 0; tm < 2; tm++) {
                LDSM4(ah[tm][0], ah[tm][1], ah[tm][2], ah[tm][3], aBH[tm] + ks * 32);
                LDSM4(al[tm][0], al[tm][1], al[tm][2], al[tm][3], aBL[tm] + ks * 32);
            }
            #pragma unroll
            for (int pp = 0; pp < 2; pp++) {
                uint32_t bh[4], bl[4];
                LDSM4(bh[0], bh[1], bh[2], bh[3], bBH[pp] + ks * 32);
                LDSM4(bl[0], bl[1], bl[2], bl[3], bBL[pp] + ks * 32);
                #pragma unroll
                for (int hf = 0; hf < 2; hf++) {
                    int tn = pp * 2 + hf;
                    #pragma unroll
                    for (int tm = 0; tm < 2; tm++) {
                        mma16816(acc[tm][tn], ah[tm], bh + 2 * hf);
                        mma16816(acc[tm][tn], ah[tm], bl + 2 * hf);
                        mma16816(acc[tm][tn], al[tm], bh + 2 * hf);
                    }
                }
            }
        }
    }
    __syncthreads();   // done reading A/W1

    // ---- stage H = relu(acc + b1) -> A region (split hi/lo), pitch PK2 ----
    #pragma unroll
    for (int tm = 0; tm < 2; tm++) {
        int m = warpM * 32 + tm * 16 + lg;
        #pragma unroll
        for (int tn = 0; tn < 4; tn++) {
            int n = warpN * 32 + tn * 8 + lt * 2;
            float2 bv = *(const float2*)(B1 + n);
            float v0 = fmaxf(acc[tm][tn][0] + bv.x, 0.f);
            float v1 = fmaxf(acc[tm][tn][1] + bv.y, 0.f);
            float v2 = fmaxf(acc[tm][tn][2] + bv.x, 0.f);
            float v3 = fmaxf(acc[tm][tn][3] + bv.y, 0.f);
            uint32_t hi, lo;
            split_pack(v0, v1, hi, lo);
            *(uint32_t*)(AH + m * PK2 + n) = hi;
            *(uint32_t*)(AL + m * PK2 + n) = lo;
            split_pack(v2, v3, hi, lo);
            *(uint32_t*)(AH + (m + 8) * PK2 + n) = hi;
            *(uint32_t*)(AL + (m + 8) * PK2 + n) = lo;
        }
    }
    // ---- load W2 (NOUT2 rows x 128) into W region (pitch PK2) ----
    for (int i = tid; i < NOUT2 * 17; i += 256) {
        int r = i / 17, c = i % 17, col = c * 8;
        float4 wh = make_float4(0.f, 0.f, 0.f, 0.f), wl = wh;
        if (col < 128) {
            wh = *(const float4*)(W2h + r * 128 + col);
            wl = *(const float4*)(W2l + r * 128 + col);
        }
        *(float4*)(WH + r * PK2 + col) = wh;
        *(float4*)(WL + r * PK2 + col) = wl;
    }
    __syncthreads();

    // ---- pass 2: 64 x NOUT2, K = 128, warp tile 32 x NOUT2/4 ----
    float acc2[2][NT2][4];
    #pragma unroll
    for (int tm = 0; tm < 2; tm++)
        #pragma unroll
        for (int tn = 0; tn < NT2; tn++)
            #pragma unroll
            for (int q = 0; q < 4; q++) acc2[tm][tn][q] = 0.f;

    {
        uint32_t aBH[2], aBL[2], bBH[NT2 / 2], bBL[NT2 / 2];
        #pragma unroll
        for (int tm = 0; tm < 2; tm++) {
            int R = warpM * 32 + tm * 16;
            aBH[tm] = uAH + ((R + a_row) * PK2 + a_col) * 2;
            aBL[tm] = uAL + ((R + a_row) * PK2 + a_col) * 2;
        }
        #pragma unroll
        for (int pp = 0; pp < NT2 / 2; pp++) {
            int N0 = warpN * (NOUT2 / 4) + pp * 16;
            bBH[pp] = uWH + ((N0 + b_row) * PK2 + b_col) * 2;
            bBL[pp] = uWL + ((N0 + b_row) * PK2 + b_col) * 2;
        }
        #pragma unroll
        for (int ks = 0; ks < 8; ks++) {
            uint32_t ah[2][4], al[2][4];
            #pragma unroll
            for (int tm = 0; tm < 2; tm++) {
                LDSM4(ah[tm][0], ah[tm][1], ah[tm][2], ah[tm][3], aBH[tm] + ks * 32);
                LDSM4(al[tm][0], al[tm][1], al[tm][2], al[tm][3], aBL[tm] + ks * 32);
            }
            #pragma unroll
            for (int pp = 0; pp < NT2 / 2; pp++) {
                uint32_t bh[4], bl[4];
                LDSM4(bh[0], bh[1], bh[2], bh[3], bBH[pp] + ks * 32);
                LDSM4(bl[0], bl[1], bl[2], bl[3], bBL[pp] + ks * 32);
                #pragma unroll
                for (int hf = 0; hf < 2; hf++) {
                    int tn = pp * 2 + hf;
                    #pragma unroll
                    for (int tm = 0; tm < 2; tm++) {
                        mma16816(acc2[tm][tn], ah[tm], bh + 2 * hf);
                        mma16816(acc2[tm][tn], ah[tm], bl + 2 * hf);
                        mma16816(acc2[tm][tn], al[tm], bh + 2 * hf);
                    }
                }
            }
        }
    }

    // ---- epilogue: Z + b2 -> global fp32 ----
    float* outF = (K1 == 32) ? (by ? g_z1t : g_z1s) : (by ? g_z2t : g_z2s);
    #pragma unroll
    for (int tm = 0; tm < 2; tm++) {
        int m = warpM * 32 + tm * 16 + lg;
        #pragma unroll
        for (int tn = 0; tn < NT2; tn++) {
            int n = warpN * (NOUT2 / 4) + tn * 8 + lt * 2;
            float2 bv = *(const float2*)(B2 + n);
            int g0 = row0 + m;
            if (g0 < N_NODES) {
                float2 o; o.x = acc2[tm][tn][0] + bv.x; o.y = acc2[tm][tn][1] + bv.y;
                *(float2*)(outF + (size_t)g0 * NOUT2 + n) = o;
            }
            int g1 = row0 + m + 8;
            if (g1 < N_NODES) {
                float2 o; o.x = acc2[tm][tn][2] + bv.x; o.y = acc2[tm][tn][3] + bv.y;
                *(float2*)(outF + (size_t)g1 * NOUT2 + n) = o;
            }
        }
    }
}

// ======================= per-graph 9x9 gram =======================
__global__ void final_kernel(float* __restrict__ out) {
    __shared__ float zs[9 * 64];
    __shared__ float zt[9 * 64];
    int g = blockIdx.x;
    const float4* ps = (const float4*)(g_z2s + (size_t)g * 9 * 64);
    const float4* pt = (const float4*)(g_z2t + (size_t)g * 9 * 64);
    int tid = threadIdx.x;
    for (int i = tid; i < 144; i += 128) {
        ((float4*)zs)[i] = ps[i];
        ((float4*)zt)[i] = pt[i];
    }
    __syncthreads();
    if (tid < 81) {
        int i = tid / 9, j = tid % 9;
        float acc = 0.f;
        #pragma unroll
        for (int k = 0; k < 64; k++) acc += zs[i * 64 + k] * zt[j * 64 + k];
        out[(g * 9 + i) * 9 + j] = acc;
    }
}

// ======================= launch =======================
extern "C" void kernel_launch(void* const* d_in, const int* in_sizes, int n_in,
                              void* d_out, int out_size) {
    const float* x  = (const float*)d_in[0];
    const int*   ei = (const int*)d_in[1];
    const float* B[2][4] = {
        { (const float*)d_in[3],  (const float*)d_in[5],  (const float*)d_in[7],  (const float*)d_in[9]  },
        { (const float*)d_in[11], (const float*)d_in[13], (const float*)d_in[15], (const float*)d_in[17] }
    };
    float* out = (float*)d_out;

    const int SMEM = (2 * 64 * 136 + 2 * 128 * 136) * 2;   // 104448 bytes -> 2 CTA/SM
    cudaFuncSetAttribute(mlp_kernel<32, 4>,  cudaFuncAttributeMaxDynamicSharedMemorySize, SMEM);
    cudaFuncSetAttribute(mlp_kernel<128, 2>, cudaFuncAttributeMaxDynamicSharedMemorySize, SMEM);

    const int GEMM_BLOCKS = (N_NODES + 63) / 64;         // 1407
    const int WARP_BLOCKS = (N_NODES * 32 + 255) / 256;
    const int SCAN_BLOCKS = (N_NODES + 1023) / 1024;     // 88

    // CSR build
    zero_kernel<<<(N_NODES + 255) / 256, 256>>>();
    hist_kernel<<<(N_EDGES + 255) / 256, 256>>>(ei);
    scan1_kernel<<<SCAN_BLOCKS, 1024>>>();
    scan2_kernel<<<1, 128>>>(SCAN_BLOCKS);
    scan3_kernel<<<SCAN_BLOCKS, 1024>>>();
    fill_kernel<<<(N_EDGES + 255) / 256, 256>>>(ei);

    // weight prep (single launch, pointers via kernel args -> capture-safe)
    prep_all_kernel<<<dim3(128, 8), 128>>>(
        (const float*)d_in[2],  (const float*)d_in[4],  (const float*)d_in[6],  (const float*)d_in[8],
        (const float*)d_in[10], (const float*)d_in[12], (const float*)d_in[14], (const float*)d_in[16]);

    agg0_kernel<<<WARP_BLOCKS, 256>>>(x);

    // layer 1 (fused MLP), both branches in one launch
    mlp_kernel<32, 4><<<dim3(GEMM_BLOCKS, 2), 256, SMEM>>>(B[0][0], B[1][0], B[0][1], B[1][1]);

    // layer 2 aggregation (both branches in one pass)
    agg1_kernel<<<WARP_BLOCKS, 256>>>();

    // layer 2 (fused MLP), both branches in one launch
    mlp_kernel<128, 2><<<dim3(GEMM_BLOCKS, 2), 256, SMEM>>>(B[0][2], B[1][2], B[0][3], B[1][3]);

    final_kernel<<<N_GRAPH, 128>>>(out);
}